// round 2
// baseline (speedup 1.0000x reference)
#include <cuda_runtime.h>
#include <math.h>

#define Bn 64
#define Ln 256
#define En 300
#define Mn 50
#define Dn 350
#define HDn 128
#define Gn 512   // 4*HD
#define Hn 256

// Scratch (device globals; no allocation allowed)
__device__ float g_gates_f[Bn*Ln*Gn];
__device__ float g_gates_b[Bn*Ln*Gn];
__device__ float g_hf[Bn*Ln*HDn];
__device__ float g_hb[Bn*Ln*HDn];
__device__ float g_cls[Bn];
__device__ float g_spsum[Bn];

__device__ __forceinline__ float sigmf(float x){ return 1.f/(1.f+expf(-x)); }
__device__ __forceinline__ float lse2(float a, float b){
    float m = fmaxf(a,b);
    return m + logf(expf(a-m)+expf(b-m));
}

// ---------------------------------------------------------------------------
// Kernel 1: fused embedding-gather + GEMM.
// C[m,n] = sum_k A[m,k]*W[n,k] + b_ih[n] + b_hh[n]
// A[m,k] = k<300 ? word_embed[sents[m],k] : mask_embed[masks[m],k-300]
// grid: (256, 8, 2)  block: 256 threads, 64x64 tile, 4x4 per thread, BK=16
// ---------------------------------------------------------------------------
__global__ void gemm_gates_kernel(const int* __restrict__ sents,
                                  const int* __restrict__ masks,
                                  const float* __restrict__ word_embed,
                                  const float* __restrict__ mask_embed,
                                  const float* __restrict__ w_ih_f,
                                  const float* __restrict__ b_ih_f,
                                  const float* __restrict__ b_hh_f,
                                  const float* __restrict__ w_ih_b,
                                  const float* __restrict__ b_ih_b,
                                  const float* __restrict__ b_hh_b) {
    const int dir = blockIdx.z;
    const float* __restrict__ W   = dir ? w_ih_b : w_ih_f;
    const float* __restrict__ bih = dir ? b_ih_b : b_ih_f;
    const float* __restrict__ bhh = dir ? b_hh_b : b_hh_f;
    float* __restrict__ C = dir ? g_gates_b : g_gates_f;

    __shared__ float As[16][64];
    __shared__ float Bs[16][64];
    __shared__ int   sid[64], mid[64];

    const int tid = threadIdx.x;
    const int m0 = blockIdx.x*64, n0 = blockIdx.y*64;
    if (tid < 64)       sid[tid]    = sents[m0+tid];
    else if (tid < 128) mid[tid-64] = masks[m0+tid-64];
    __syncthreads();

    const int ty = tid >> 4, tx = tid & 15;
    const int kidx = tid & 15;
    const int row16 = tid >> 4;
    float acc[4][4];
    #pragma unroll
    for (int i=0;i<4;i++)
        #pragma unroll
        for (int j=0;j<4;j++) acc[i][j]=0.f;

    for (int k0 = 0; k0 < Dn; k0 += 16) {
        const int k = k0 + kidx;
        const bool kok = (k < Dn);
        #pragma unroll
        for (int p = 0; p < 4; p++) {
            const int mr = row16 + p*16;
            float v = 0.f, w = 0.f;
            if (kok) {
                v = (k < En) ? word_embed[(size_t)sid[mr]*En + k]
                             : mask_embed[(size_t)mid[mr]*Mn + (k - En)];
                w = W[(size_t)(n0 + mr)*Dn + k];
            }
            As[kidx][mr] = v;
            Bs[kidx][mr] = w;
        }
        __syncthreads();
        #pragma unroll
        for (int kk = 0; kk < 16; kk++) {
            float4 a  = *(const float4*)&As[kk][ty*4];
            float4 bv = *(const float4*)&Bs[kk][tx*4];
            float av[4] = {a.x,a.y,a.z,a.w};
            float bb[4] = {bv.x,bv.y,bv.z,bv.w};
            #pragma unroll
            for (int i=0;i<4;i++)
                #pragma unroll
                for (int j=0;j<4;j++)
                    acc[i][j] += av[i]*bb[j];
        }
        __syncthreads();
    }
    #pragma unroll
    for (int i=0;i<4;i++){
        const int m = m0 + ty*4 + i;
        float4 o;
        float* op = &o.x;
        #pragma unroll
        for (int j=0;j<4;j++){
            const int n = n0 + tx*4 + j;
            op[j] = acc[i][j] + bih[n] + bhh[n];
        }
        *(float4*)&C[(size_t)m*Gn + n0 + tx*4] = o;
    }
}

// ---------------------------------------------------------------------------
// Kernel 2: LSTM recurrence, both directions in one launch.
// grid: 64 blocks (32 per dir), 512 threads; block handles 2 batch rows.
// Thread g computes gate g (dot of h[128] with w_hh row g) for both rows.
// ---------------------------------------------------------------------------
__global__ void lstm_kernel(const float* __restrict__ w_hh_f,
                            const float* __restrict__ w_hh_b,
                            const int* __restrict__ lens) {
    const int dir = (blockIdx.x >= Bn/2) ? 1 : 0;
    const int rb  = blockIdx.x - dir*(Bn/2);
    const float* __restrict__ w_hh     = dir ? w_hh_b  : w_hh_f;
    const float* __restrict__ gates_in = dir ? g_gates_b : g_gates_f;
    float* __restrict__ h_out          = dir ? g_hb : g_hf;

    __shared__ float hs[2][HDn];
    __shared__ float cs[2][HDn];
    __shared__ float gbuf[2][Gn];

    const int g = threadIdx.x;               // [0,512)
    const int r0 = rb*2;
    const int len0 = lens[r0], len1 = lens[r0+1];
    const int maxlen = max(len0, len1);

    if (g < 2*HDn) { hs[g>>7][g&127] = 0.f; cs[g>>7][g&127] = 0.f; }
    __syncthreads();

    const float4* __restrict__ wrow = (const float4*)(w_hh + (size_t)g*HDn);

    for (int t = 0; t < maxlen; t++) {
        float acc0 = 0.f, acc1 = 0.f;
        #pragma unroll 8
        for (int k4 = 0; k4 < HDn/4; k4++) {
            const float4 w  = wrow[k4];
            const float4 h0 = *(const float4*)&hs[0][k4*4];
            const float4 h1 = *(const float4*)&hs[1][k4*4];
            acc0 += w.x*h0.x + w.y*h0.y + w.z*h0.z + w.w*h0.w;
            acc1 += w.x*h1.x + w.y*h1.y + w.z*h1.z + w.w*h1.w;
        }
        const int u0 = dir ? (len0-1-t) : t;
        const int u1 = dir ? (len1-1-t) : t;
        if (t < len0) gbuf[0][g] = acc0 + gates_in[((size_t)r0*Ln + u0)*Gn + g];
        if (t < len1) gbuf[1][g] = acc1 + gates_in[((size_t)(r0+1)*Ln + u1)*Gn + g];
        __syncthreads();
        if (g < 2*HDn) {
            const int r = g>>7, j = g&127;
            const int lenr = r ? len1 : len0;
            if (t < lenr) {
                const float gi = gbuf[r][j];
                const float gf = gbuf[r][HDn+j];
                const float gc = gbuf[r][2*HDn+j];
                const float go = gbuf[r][3*HDn+j];
                const float c = sigmf(gf)*cs[r][j] + sigmf(gi)*tanhf(gc);
                const float h = sigmf(go)*tanhf(c);
                cs[r][j] = c; hs[r][j] = h;
                const int u = r ? u1 : u0;
                h_out[((size_t)(r0+r)*Ln + u)*HDn + j] = h;
            }
        }
        __syncthreads();
    }
}

// ---------------------------------------------------------------------------
// Kernel 3: per-row tavg + emit + CRF forward/backward + marginals + classifier.
// grid: 64 blocks, 256 threads.
// ---------------------------------------------------------------------------
__global__ void crf_kernel(const int* __restrict__ masks,
                           const int* __restrict__ lens,
                           const int* __restrict__ labels,
                           const float* __restrict__ f2t_w,
                           const float* __restrict__ f2t_b,
                           const float* __restrict__ trans,
                           const float* __restrict__ f2l_w,
                           const float* __restrict__ f2l_b) {
    const int b = blockIdx.x;
    const int tid = threadIdx.x; // 256

    __shared__ float tv[Hn];
    __shared__ float fw[2*Hn];
    __shared__ float em[Ln][2];
    __shared__ float al[Ln][2];
    __shared__ float be[Ln][2];
    __shared__ float sp[Ln];
    __shared__ float red[Hn];
    __shared__ int   msk[Ln];
    __shared__ float Ts[4];
    __shared__ float logZ_s, sumsp_s, scores[3];

    const int len = lens[b];
    msk[tid] = masks[b*Ln + tid];
    fw[tid]      = f2t_w[tid];
    fw[Hn + tid] = f2t_w[Hn + tid];
    if (tid < 4) Ts[tid] = trans[tid];
    __syncthreads();

    const float* __restrict__ hfb = g_hf + (size_t)b*Ln*HDn;
    const float* __restrict__ hbb = g_hb + (size_t)b*Ln*HDn;

    // tavg over masked positions (count all mask=1; context=0 beyond len)
    float num = 0.f; int cnt = 0;
    for (int l = 0; l < Ln; l++) {
        const int mf = msk[l];
        if (mf) {
            cnt += mf;
            if (l < len) {
                const float ctx = (tid < HDn) ? hfb[l*HDn + tid] : hbb[l*HDn + tid - HDn];
                num += ctx * (float)mf;
            }
        }
    }
    tv[tid] = num / (float)cnt;
    __syncthreads();

    // emit[l][s] = dot(context[l]+tavg, f2t_w[s]) + f2t_b[s]
    if (tid < len) {
        float e0 = f2t_b[0], e1 = f2t_b[1];
        const float* hrow = hfb + tid*HDn;
        #pragma unroll 4
        for (int hh = 0; hh < HDn; hh++) {
            const float c = hrow[hh] + tv[hh];
            e0 += c*fw[hh]; e1 += c*fw[Hn+hh];
        }
        const float* hrow2 = hbb + tid*HDn;
        #pragma unroll 4
        for (int hh = 0; hh < HDn; hh++) {
            const float c = hrow2[hh] + tv[HDn+hh];
            e0 += c*fw[HDn+hh]; e1 += c*fw[Hn+HDn+hh];
        }
        em[tid][0] = e0; em[tid][1] = e1;
    }
    __syncthreads();

    // serial alpha/beta recursions (2 states)
    if (tid == 0) {
        al[0][0]=em[0][0]; al[0][1]=em[0][1];
        for (int t = 1; t < len; t++) {
            const float a0 = al[t-1][0], a1 = al[t-1][1];
            al[t][0] = em[t][0] + lse2(a0+Ts[0], a1+Ts[2]);
            al[t][1] = em[t][1] + lse2(a0+Ts[1], a1+Ts[3]);
        }
        logZ_s = lse2(al[len-1][0], al[len-1][1]);
        be[len-1][0]=0.f; be[len-1][1]=0.f;
        for (int t = len-2; t >= 0; t--) {
            const float x0 = em[t+1][0]+be[t+1][0];
            const float x1 = em[t+1][1]+be[t+1][1];
            be[t][0] = lse2(Ts[0]+x0, Ts[1]+x1);
            be[t][1] = lse2(Ts[2]+x0, Ts[3]+x1);
        }
    }
    __syncthreads();

    sp[tid] = (tid < len) ? expf(al[tid][1]+be[tid][1]-logZ_s) : 0.f;
    __syncthreads();

    // deterministic tree reduction for sum_sp
    red[tid] = sp[tid];
    __syncthreads();
    for (int s = 128; s > 0; s >>= 1) {
        if (tid < s) red[tid] += red[tid+s];
        __syncthreads();
    }
    if (tid == 0) sumsp_s = red[0];
    __syncthreads();
    const float sum_sp = sumsp_s;

    // sent_v[h] = sum_l sp[l]*context[l][h] + sum_sp*tavg[h]
    float s1 = 0.f;
    for (int l = 0; l < len; l++) {
        const float ctx = (tid < HDn) ? hfb[l*HDn + tid] : hbb[l*HDn + tid - HDn];
        s1 += sp[l]*ctx;
    }
    const float svh = s1 + sum_sp * tv[tid];

    // label scores (3 deterministic dot reductions)
    for (int c = 0; c < 3; c++) {
        red[tid] = svh * f2l_w[c*Hn + tid];
        __syncthreads();
        for (int s = 128; s > 0; s >>= 1) {
            if (tid < s) red[tid] += red[tid+s];
            __syncthreads();
        }
        if (tid == 0) scores[c] = red[0] + f2l_b[c];
        __syncthreads();
    }

    if (tid == 0) {
        const float m = fmaxf(scores[0], fmaxf(scores[1], scores[2]));
        const float lse = m + logf(expf(scores[0]-m)+expf(scores[1]-m)+expf(scores[2]-m));
        g_cls[b]   = lse - scores[labels[b]];  // -logp[label]
        g_spsum[b] = sum_sp;
    }
}

// ---------------------------------------------------------------------------
// Kernel 4: deterministic final reduction -> out[0]=cls_loss, out[1]=norm_pen
// ---------------------------------------------------------------------------
__global__ void finalize_kernel(const float* __restrict__ trans,
                                float* __restrict__ out) {
    if (threadIdx.x == 0) {
        float cs = 0.f, ss = 0.f;
        for (int b = 0; b < Bn; b++) { cs += g_cls[b]; ss += g_spsum[b]; }
        const float pena = fmaxf(trans[2]-trans[0], 0.f) + fmaxf(trans[1]-trans[3], 0.f);
        out[0] = cs / (float)Bn;
        out[1] = 1.0f*pena + 0.1f*(ss/(float)Bn);
    }
}

extern "C" void kernel_launch(void* const* d_in, const int* in_sizes, int n_in,
                              void* d_out, int out_size) {
    const int*   sents      = (const int*)d_in[0];
    const int*   masks      = (const int*)d_in[1];
    const int*   labels     = (const int*)d_in[2];
    const int*   lens       = (const int*)d_in[3];
    const float* word_embed = (const float*)d_in[4];
    const float* mask_embed = (const float*)d_in[5];
    const float* w_ih_f     = (const float*)d_in[6];
    const float* w_hh_f     = (const float*)d_in[7];
    const float* b_ih_f     = (const float*)d_in[8];
    const float* b_hh_f     = (const float*)d_in[9];
    const float* w_ih_b     = (const float*)d_in[10];
    const float* w_hh_b     = (const float*)d_in[11];
    const float* b_ih_b     = (const float*)d_in[12];
    const float* b_hh_b     = (const float*)d_in[13];
    const float* f2t_w      = (const float*)d_in[14];
    const float* f2t_b      = (const float*)d_in[15];
    const float* trans      = (const float*)d_in[16];
    const float* f2l_w      = (const float*)d_in[17];
    const float* f2l_b      = (const float*)d_in[18];
    float* out = (float*)d_out;

    dim3 ggrid(Bn*Ln/64, Gn/64, 2);
    gemm_gates_kernel<<<ggrid, 256>>>(sents, masks, word_embed, mask_embed,
                                      w_ih_f, b_ih_f, b_hh_f,
                                      w_ih_b, b_ih_b, b_hh_b);
    lstm_kernel<<<Bn, 512>>>(w_hh_f, w_hh_b, lens);
    crf_kernel<<<Bn, 256>>>(masks, lens, labels, f2t_w, f2t_b, trans, f2l_w, f2l_b);
    finalize_kernel<<<1, 32>>>(trans, out);
}